// round 2
// baseline (speedup 1.0000x reference)
#include <cuda_runtime.h>
#include <cuda_bf16.h>
#include <cstdint>

// Problem constants
#define H 256
#define B_ 2
#define T_ 1024
#define S_ 4
#define R_ 32
#define V_ 1023            // T - NG + 1, NG=2
#define M_ 8
#define ROUTE_VOCAB 65536
#define SUB_STRIDE  (R_ * ROUTE_VOCAB)   // 2097152

// GEMM dims: C[2048 x 1024] = hidden[2048 x 256] @ W^T, W = q_weight viewed as [1024 x 256]
#define GM 2048
#define GN 1024
#define GK 256

#define BM 64
#define BN 64
#define BK 16
#define TM 4
#define TN 8
// threads per block = (BM/TM) * (BN/TN) = 16 * 8 = 128

// Scratch: packed sign codes, layout [(b*S+s)*T + t]*R + r, uint8
__device__ unsigned char g_codes[B_ * S_ * T_ * R_];

__global__ __launch_bounds__(128, 8)
void gemm_sign_kernel(const float* __restrict__ A,   // hidden [2048,256]
                      const float* __restrict__ W)   // q_weight [1024,256]
{
    __shared__ float As[BK][BM + 4];
    __shared__ float Bs[BK][BN + 4];

    const int tid = threadIdx.x;
    const int tx = tid & 15;     // row group: rows tx*4 .. tx*4+3
    const int ty = tid >> 4;     // col group: cols ty*8 .. ty*8+7
    const int bm = blockIdx.y * BM;
    const int bn = blockIdx.x * BN;

    float acc[TM][TN];
#pragma unroll
    for (int i = 0; i < TM; i++)
#pragma unroll
        for (int j = 0; j < TN; j++) acc[i][j] = 0.0f;

    for (int k0 = 0; k0 < GK; k0 += BK) {
        // Load tiles: 64 rows x 16 k-floats = 256 float4 per operand, 128 threads -> 2 each.
#pragma unroll
        for (int l = 0; l < 2; l++) {
            int f   = tid + l * 128;     // 0..255
            int row = f >> 2;            // 0..63
            int kc  = (f & 3) * 4;       // 0,4,8,12
            float4 va = *(const float4*)&A[(size_t)(bm + row) * GK + k0 + kc];
            As[kc + 0][row] = va.x;
            As[kc + 1][row] = va.y;
            As[kc + 2][row] = va.z;
            As[kc + 3][row] = va.w;
            float4 vb = *(const float4*)&W[(size_t)(bn + row) * GK + k0 + kc];
            Bs[kc + 0][row] = vb.x;
            Bs[kc + 1][row] = vb.y;
            Bs[kc + 2][row] = vb.z;
            Bs[kc + 3][row] = vb.w;
        }
        __syncthreads();

#pragma unroll
        for (int k = 0; k < BK; ++k) {
            float4 a0 = *(const float4*)&As[k][tx * 4];
            float4 b0 = *(const float4*)&Bs[k][ty * 8];
            float4 b1 = *(const float4*)&Bs[k][ty * 8 + 4];
            float a[TM] = {a0.x, a0.y, a0.z, a0.w};
            float b[TN] = {b0.x, b0.y, b0.z, b0.w, b1.x, b1.y, b1.z, b1.w};
#pragma unroll
            for (int i = 0; i < TM; i++)
#pragma unroll
                for (int j = 0; j < TN; j++)
                    acc[i][j] = fmaf(a[i], b[j], acc[i][j]);
        }
        __syncthreads();
    }

    // Pack signs: each thread's 8 columns are one code byte (n0 multiple of 8).
    const int n0 = bn + ty * 8;
    const int s  = n0 >> 8;
    const int r  = (n0 & 255) >> 3;
#pragma unroll
    for (int i = 0; i < TM; i++) {
        unsigned byte = 0;
#pragma unroll
        for (int j = 0; j < TN; j++)
            byte |= (acc[i][j] > 0.0f) ? (1u << j) : 0u;
        int m = bm + tx * 4 + i;         // m = b*1024 + t
        int b = m >> 10;
        int t = m & 1023;
        g_codes[(((b * S_ + s) * T_) + t) * R_ + r] = (unsigned char)byte;
    }
}

// 2 threads per gather row: each handles 16B. Total threads = B*S*V*R*2 = 523776 = 2046*256.
__global__ __launch_bounds__(256)
void gather_kernel(const float* __restrict__ flat,   // [8388608, 8]
                   float* __restrict__ out)          // [2,4,1023,256]
{
    int idx  = blockIdx.x * blockDim.x + threadIdx.x;
    int half = idx & 1;
    int row  = idx >> 1;                 // ((b*S+s)*V + v)*R + r
    int r    = row & 31;
    int q    = row >> 5;                 // bs*V + v
    int v    = q % V_;
    int bs   = q / V_;                   // b*S + s
    int s    = bs & 3;

    const unsigned char* cp = g_codes + ((size_t)(bs * T_ + v) * R_) + r;
    unsigned c0 = cp[0];
    unsigned c1 = cp[R_];                // codes at v+1, same (bs, r)
    unsigned addr = c0 | (c1 << 8);

    unsigned gidx = (unsigned)s * (unsigned)SUB_STRIDE
                  + (unsigned)r * (unsigned)ROUTE_VOCAB + addr;

    const float4* src = (const float4*)(flat + (size_t)gidx * M_) + half;
    float4        val = __ldg(src);
    float4*       dst = (float4*)(out + (size_t)row * M_) + half;
    *dst = val;
}

extern "C" void kernel_launch(void* const* d_in, const int* in_sizes, int n_in,
                              void* d_out, int out_size)
{
    (void)in_sizes; (void)n_in; (void)out_size;
    const float* hidden = (const float*)d_in[0];   // [2,1024,256]
    const float* qw     = (const float*)d_in[1];   // [4,256,256]
    const float* fw     = (const float*)d_in[2];   // [8388608,8]
    float* out          = (float*)d_out;           // [2,4,1023,256]

    dim3 grid(GN / BN, GM / BM);   // (16, 32)
    gemm_sign_kernel<<<grid, 128>>>(hidden, qw);

    gather_kernel<<<2046, 256>>>(fw, out);
}

// round 4
// speedup vs baseline: 1.0007x; 1.0007x over previous
#include <cuda_runtime.h>
#include <cuda_bf16.h>
#include <cstdint>

// ---------------- problem constants ----------------
#define B_ 2
#define T_ 1024
#define S_ 4
#define R_ 32
#define V_ 1023
#define M_ 8
#define ROUTE_VOCAB 65536
#define SUB_STRIDE  (R_ * ROUTE_VOCAB)

#define GM 2048
#define GN 1024
#define GK 256

// ---------------- mma.sync GEMM tiling ----------------
#define BM 128
#define BN 128
#define BK 32
#define NPROD 6
#define NK   (NPROD * GK / BK)     // 48 chunk iterations
#define STAGES 4
#define ROWB 80                    // smem bytes per row: 64B data + 16B pad (conflict-free)
#define STAGE_A (BM * ROWB)        // 10240
#define STAGE_B (BN * ROWB)        // 10240
#define STAGE_SZ (STAGE_A + STAGE_B)
#define SMEM_SZ (STAGES * STAGE_SZ)   // 81920

// ---------------- device scratch ----------------
__device__ __nv_bfloat16 gA[3u * GM * GK];     // A limbs [l][m][k]
__device__ __nv_bfloat16 gW[3u * GN * GK];     // W limbs [l][n][k]
__device__ __align__(16) unsigned char g_codes[B_ * S_ * T_ * R_];

__device__ __forceinline__ uint32_t smem_u32(const void* p) {
    uint32_t a;
    asm("{ .reg .u64 t; cvta.to.shared.u64 t, %1; cvt.u32.u64 %0, t; }" : "=r"(a) : "l"(p));
    return a;
}

// ---------------- kernel 1: fp32 -> 3x bf16 limb split ----------------
__global__ __launch_bounds__(256) void split_kernel(const float* __restrict__ A,
                                                    const float* __restrict__ W)
{
    const int NA4 = GM * GK / 4;
    const int NW4 = GN * GK / 4;
    int i = blockIdx.x * blockDim.x + threadIdx.x;
    const float* src; __nv_bfloat16* dst; int b4, plane4;
    if (i < NA4)            { src = A; dst = gA; b4 = i;       plane4 = NA4; }
    else if (i < NA4 + NW4) { src = W; dst = gW; b4 = i - NA4; plane4 = NW4; }
    else return;

    float4 v = ((const float4*)src)[b4];
    float a[4] = {v.x, v.y, v.z, v.w};
    unsigned short l0[4], l1[4], l2[4];
#pragma unroll
    for (int j = 0; j < 4; j++) {
        __nv_bfloat16 h0 = __float2bfloat16_rn(a[j]);
        float r1 = a[j] - __bfloat162float(h0);
        __nv_bfloat16 h1 = __float2bfloat16_rn(r1);
        float r2 = r1 - __bfloat162float(h1);
        __nv_bfloat16 h2 = __float2bfloat16_rn(r2);
        l0[j] = __bfloat16_as_ushort(h0);
        l1[j] = __bfloat16_as_ushort(h1);
        l2[j] = __bfloat16_as_ushort(h2);
    }
    uint2* d2 = (uint2*)dst;
    uint2 u;
    u.x = (uint32_t)l0[0] | ((uint32_t)l0[1] << 16); u.y = (uint32_t)l0[2] | ((uint32_t)l0[3] << 16);
    d2[0 * plane4 + b4] = u;
    u.x = (uint32_t)l1[0] | ((uint32_t)l1[1] << 16); u.y = (uint32_t)l1[2] | ((uint32_t)l1[3] << 16);
    d2[1 * plane4 + b4] = u;
    u.x = (uint32_t)l2[0] | ((uint32_t)l2[1] << 16); u.y = (uint32_t)l2[2] | ((uint32_t)l2[3] << 16);
    d2[2 * plane4 + b4] = u;
}

// ---------------- kernel 2: mma.sync bf16 GEMM + sign pack ----------------
__constant__ int cPA[NPROD] = {0, 0, 1, 1, 0, 2};
__constant__ int cPW[NPROD] = {0, 1, 0, 1, 2, 0};

__device__ __forceinline__ void load_stage(uint32_t sbase, int c, int bm, int bn, int tid)
{
    int p  = c >> 3;
    int k0 = (c & 7) * BK;
    const __nv_bfloat16* bA = gA + (size_t)cPA[p] * GM * GK + (size_t)bm * GK + k0;
    const __nv_bfloat16* bW = gW + (size_t)cPW[p] * GN * GK + (size_t)bn * GK + k0;
    uint32_t stg = sbase + (uint32_t)(c % STAGES) * STAGE_SZ;
#pragma unroll
    for (int j = 0; j < 2; ++j) {
        int id  = tid + j * 256;          // 0..511
        int row = id >> 2;
        int c4  = id & 3;
        uint32_t da = stg + (uint32_t)(row * ROWB + c4 * 16);
        asm volatile("cp.async.cg.shared.global [%0], [%1], 16;"
                     :: "r"(da), "l"(bA + (size_t)row * GK + c4 * 8));
        uint32_t db = stg + STAGE_A + (uint32_t)(row * ROWB + c4 * 16);
        asm volatile("cp.async.cg.shared.global [%0], [%1], 16;"
                     :: "r"(db), "l"(bW + (size_t)row * GK + c4 * 8));
    }
    asm volatile("cp.async.commit_group;" ::: "memory");
}

__global__ __launch_bounds__(256, 1)
void gemm_mma_kernel()
{
    extern __shared__ __align__(16) char smem[];
    const uint32_t sbase = smem_u32(smem);
    const int tid  = threadIdx.x;
    const int w    = tid >> 5;
    const int lane = tid & 31;
    const int bm = blockIdx.y * BM, bn = blockIdx.x * BN;
    const int wm = (w & 1) * 64;          // warp m offset in tile
    const int wn = (w >> 1) * 32;         // warp n offset in tile

    // per-lane ldmatrix address components
    const int lrow = lane & 7;
    const int lmat = lane >> 3;
    const int a_roff = (lmat & 1) * 8 + lrow;     // row within m16
    const int a_koff = (lmat >> 1) * 16;          // byte offset for k8 half
    const int l16  = lane & 15;
    const int b_roff = l16 & 7;
    const int b_koff = (l16 >> 3) * 16;

    float acc[4][4][4];
#pragma unroll
    for (int i = 0; i < 4; i++)
#pragma unroll
        for (int j = 0; j < 4; j++)
#pragma unroll
            for (int q = 0; q < 4; q++) acc[i][j][q] = 0.0f;

    load_stage(sbase, 0, bm, bn, tid);
    load_stage(sbase, 1, bm, bn, tid);
    load_stage(sbase, 2, bm, bn, tid);

    for (int c = 0; c < NK; ++c) {
        asm volatile("cp.async.wait_group 2;" ::: "memory");
        __syncthreads();
        if (c + 3 < NK) load_stage(sbase, c + 3, bm, bn, tid);

        uint32_t aS = sbase + (uint32_t)(c % STAGES) * STAGE_SZ;
        uint32_t bS = aS + STAGE_A;

#pragma unroll
        for (int kk = 0; kk < 2; ++kk) {
            uint32_t af[4][4];
            uint32_t bf[4][2];
#pragma unroll
            for (int mt = 0; mt < 4; ++mt) {
                uint32_t addr = aS + (uint32_t)((wm + mt * 16 + a_roff) * ROWB + kk * 32 + a_koff);
                asm volatile("ldmatrix.sync.aligned.m8n8.x4.shared.b16 {%0,%1,%2,%3}, [%4];"
                             : "=r"(af[mt][0]), "=r"(af[mt][1]), "=r"(af[mt][2]), "=r"(af[mt][3])
                             : "r"(addr));
            }
#pragma unroll
            for (int nt = 0; nt < 4; ++nt) {
                uint32_t addr = bS + (uint32_t)((wn + nt * 8 + b_roff) * ROWB + kk * 32 + b_koff);
                asm volatile("ldmatrix.sync.aligned.m8n8.x2.shared.b16 {%0,%1}, [%2];"
                             : "=r"(bf[nt][0]), "=r"(bf[nt][1])
                             : "r"(addr));
            }
#pragma unroll
            for (int mt = 0; mt < 4; ++mt)
#pragma unroll
                for (int nt = 0; nt < 4; ++nt) {
                    asm volatile(
                        "mma.sync.aligned.m16n8k16.row.col.f32.bf16.bf16.f32 "
                        "{%0,%1,%2,%3},{%4,%5,%6,%7},{%8,%9},{%0,%1,%2,%3};"
                        : "+f"(acc[mt][nt][0]), "+f"(acc[mt][nt][1]),
                          "+f"(acc[mt][nt][2]), "+f"(acc[mt][nt][3])
                        : "r"(af[mt][0]), "r"(af[mt][1]), "r"(af[mt][2]), "r"(af[mt][3]),
                          "r"(bf[nt][0]), "r"(bf[nt][1]));
                }
        }
    }

    // ---- epilogue: sign pack. n-tile (8 cols) == one code byte. ----
    // spack[row][bytecol]: 128 x 16 bytes staged in smem (stage area reused).
    __syncthreads();   // all compute done before overwriting stage 0
    unsigned char* spack = (unsigned char*)smem;
    const int bytecol = (wn >> 3);   // + nt
#pragma unroll
    for (int mt = 0; mt < 4; ++mt) {
#pragma unroll
        for (int nt = 0; nt < 4; ++nt) {
            unsigned v0 = ((acc[mt][nt][0] > 0.0f) ? 1u : 0u) | ((acc[mt][nt][1] > 0.0f) ? 2u : 0u);
            unsigned v1 = ((acc[mt][nt][2] > 0.0f) ? 1u : 0u) | ((acc[mt][nt][3] > 0.0f) ? 2u : 0u);
            v0 <<= 2 * (lane & 3);
            v1 <<= 2 * (lane & 3);
            v0 |= __shfl_xor_sync(0xffffffffu, v0, 1);
            v0 |= __shfl_xor_sync(0xffffffffu, v0, 2);
            v1 |= __shfl_xor_sync(0xffffffffu, v1, 1);
            v1 |= __shfl_xor_sync(0xffffffffu, v1, 2);
            if ((lane & 3) == 0) {
                int r = lane >> 2;                       // 0..7
                int row0 = wm + mt * 16 + r;
                spack[row0 * 16 + bytecol + nt]       = (unsigned char)v0;
                spack[(row0 + 8) * 16 + bytecol + nt] = (unsigned char)v1;
            }
        }
    }
    __syncthreads();

    if (tid < BM) {
        int mg = bm + tid;
        int b  = mg >> 10;
        int t  = mg & 1023;
        int sc = bn >> 8;
        int r0 = (bn & 255) >> 3;      // 0 or 16
        uint4 val = *(uint4*)(spack + tid * 16);
        *(uint4*)(g_codes + ((size_t)((b * S_ + sc) * T_ + t) * R_) + r0) = val;
    }
}

// ---------------- kernel 3: gather ----------------
__global__ __launch_bounds__(256)
void gather_kernel(const float* __restrict__ flat, float* __restrict__ out)
{
    int idx  = blockIdx.x * blockDim.x + threadIdx.x;
    int half = idx & 1;
    int row  = idx >> 1;
    int r    = row & 31;
    int q    = row >> 5;
    int v    = q % V_;
    int bs   = q / V_;
    int s    = bs & 3;

    const unsigned char* cp = g_codes + ((size_t)(bs * T_ + v) * R_) + r;
    unsigned c0 = cp[0];
    unsigned c1 = cp[R_];
    unsigned addr = c0 | (c1 << 8);

    unsigned gidx = (unsigned)s * (unsigned)SUB_STRIDE
                  + (unsigned)r * (unsigned)ROUTE_VOCAB + addr;

    const float4* src = (const float4*)(flat + (size_t)gidx * M_) + half;
    float4 val = __ldg(src);
    float4* dstp = (float4*)(out + (size_t)row * M_) + half;
    *dstp = val;
}

// ---------------- launch ----------------
extern "C" void kernel_launch(void* const* d_in, const int* in_sizes, int n_in,
                              void* d_out, int out_size)
{
    (void)in_sizes; (void)n_in; (void)out_size;
    const float* hidden = (const float*)d_in[0];
    const float* qw     = (const float*)d_in[1];
    const float* fw     = (const float*)d_in[2];
    float* out          = (float*)d_out;

    cudaFuncSetAttribute(gemm_mma_kernel, cudaFuncAttributeMaxDynamicSharedMemorySize, SMEM_SZ);

    split_kernel<<<(GM * GK / 4 + GN * GK / 4 + 255) / 256, 256>>>(hidden, qw);

    dim3 grid(GN / BN, GM / BM);   // (8, 16) = 128 CTAs
    gemm_mma_kernel<<<grid, 256, SMEM_SZ>>>();

    gather_kernel<<<2046, 256>>>(fw, out);
}

// round 7
// speedup vs baseline: 1.1486x; 1.1477x over previous
#include <cuda_runtime.h>
#include <cuda_bf16.h>
#include <cstdint>

// ---------------- problem constants ----------------
#define B_ 2
#define T_ 1024
#define S_ 4
#define R_ 32
#define V_ 1023
#define M_ 8
#define ROUTE_VOCAB 65536
#define SUB_STRIDE  (R_ * ROUTE_VOCAB)

#define GM 2048
#define GN 1024
#define GK 256

// ---------------- mma.sync GEMM tiling (1 product) ----------------
#define BM 128
#define BN 128
#define BK 32
#define NK (GK / BK)               // 8 chunk iterations
#define STAGES 4
#define ROWB 80                    // smem bytes/row: 64B data + 16B pad (conflict-free)
#define STAGE_A (BM * ROWB)
#define STAGE_B (BN * ROWB)
#define STAGE_SZ (STAGE_A + STAGE_B)
#define SMEM_SZ (STAGES * STAGE_SZ)   // 81920

#define TAU 0.005f
#define FLAG_CAP 131072
#define LF_CAP 8

// ---------------- device scratch ----------------
__device__ __nv_bfloat16 gA[GM * GK];          // bf16 round of hidden
__device__ __nv_bfloat16 gW[GN * GK];          // bf16 round of q_weight
__device__ __align__(16) unsigned char g_codes[B_ * S_ * T_ * R_];
__device__ unsigned int g_nflags;
__device__ unsigned int g_flags[FLAG_CAP];     // (m << 10) | n

__device__ __forceinline__ uint32_t smem_u32(const void* p) {
    uint32_t a;
    asm("{ .reg .u64 t; cvta.to.shared.u64 t, %1; cvt.u32.u64 %0, t; }" : "=r"(a) : "l"(p));
    return a;
}

// ---------------- kernel 1: fp32 -> bf16 round + counter reset ----------------
__global__ __launch_bounds__(256) void split_kernel(const float* __restrict__ A,
                                                    const float* __restrict__ W)
{
    if (blockIdx.x == 0 && threadIdx.x == 0) g_nflags = 0;
    const int NA4 = GM * GK / 4;   // 131072
    const int NW4 = GN * GK / 4;   // 65536
    int base = (blockIdx.x * blockDim.x + threadIdx.x) * 2;
#pragma unroll
    for (int u = 0; u < 2; ++u) {
        int i = base + u;
        const float* src; __nv_bfloat16* dst; int b4;
        if (i < NA4)            { src = A; dst = gA; b4 = i; }
        else if (i < NA4 + NW4) { src = W; dst = gW; b4 = i - NA4; }
        else continue;
        float4 v = ((const float4*)src)[b4];
        unsigned short l0 = __bfloat16_as_ushort(__float2bfloat16_rn(v.x));
        unsigned short l1 = __bfloat16_as_ushort(__float2bfloat16_rn(v.y));
        unsigned short l2 = __bfloat16_as_ushort(__float2bfloat16_rn(v.z));
        unsigned short l3 = __bfloat16_as_ushort(__float2bfloat16_rn(v.w));
        uint2 u2;
        u2.x = (uint32_t)l0 | ((uint32_t)l1 << 16);
        u2.y = (uint32_t)l2 | ((uint32_t)l3 << 16);
        ((uint2*)dst)[b4] = u2;
    }
}

// ---------------- kernel 2: mma.sync bf16 GEMM + sign pack + flag ----------------
__device__ __forceinline__ void load_stage(uint32_t sbase, int c, int bm, int bn, int tid)
{
    int k0 = c * BK;
    const __nv_bfloat16* bA = gA + (size_t)bm * GK + k0;
    const __nv_bfloat16* bW = gW + (size_t)bn * GK + k0;
    uint32_t stg = sbase + (uint32_t)(c % STAGES) * STAGE_SZ;
#pragma unroll
    for (int j = 0; j < 2; ++j) {
        int id  = tid + j * 256;
        int row = id >> 2;
        int c4  = id & 3;
        uint32_t da = stg + (uint32_t)(row * ROWB + c4 * 16);
        asm volatile("cp.async.cg.shared.global [%0], [%1], 16;"
                     :: "r"(da), "l"(bA + (size_t)row * GK + c4 * 8));
        uint32_t db = stg + STAGE_A + (uint32_t)(row * ROWB + c4 * 16);
        asm volatile("cp.async.cg.shared.global [%0], [%1], 16;"
                     :: "r"(db), "l"(bW + (size_t)row * GK + c4 * 8));
    }
    asm volatile("cp.async.commit_group;" ::: "memory");
}

__global__ __launch_bounds__(256, 1)
void gemm_mma_kernel()
{
    extern __shared__ __align__(16) char smem[];
    const uint32_t sbase = smem_u32(smem);
    const int tid  = threadIdx.x;
    const int w    = tid >> 5;
    const int lane = tid & 31;
    const int bm = blockIdx.y * BM, bn = blockIdx.x * BN;
    const int wm = (w & 1) * 64;
    const int wn = (w >> 1) * 32;

    const int lrow = lane & 7;
    const int lmat = lane >> 3;
    const int a_roff = (lmat & 1) * 8 + lrow;
    const int a_koff = (lmat >> 1) * 16;
    const int l16  = lane & 15;
    const int b_roff = l16 & 7;
    const int b_koff = (l16 >> 3) * 16;

    float acc[4][4][4];
#pragma unroll
    for (int i = 0; i < 4; i++)
#pragma unroll
        for (int j = 0; j < 4; j++)
#pragma unroll
            for (int q = 0; q < 4; q++) acc[i][j][q] = 0.0f;

    load_stage(sbase, 0, bm, bn, tid);
    load_stage(sbase, 1, bm, bn, tid);
    load_stage(sbase, 2, bm, bn, tid);

    for (int c = 0; c < NK; ++c) {
        asm volatile("cp.async.wait_group 2;" ::: "memory");
        __syncthreads();
        if (c + 3 < NK) load_stage(sbase, c + 3, bm, bn, tid);

        uint32_t aS = sbase + (uint32_t)(c % STAGES) * STAGE_SZ;
        uint32_t bS = aS + STAGE_A;

#pragma unroll
        for (int kk = 0; kk < 2; ++kk) {
            uint32_t af[4][4];
            uint32_t bf[4][2];
#pragma unroll
            for (int mt = 0; mt < 4; ++mt) {
                uint32_t addr = aS + (uint32_t)((wm + mt * 16 + a_roff) * ROWB + kk * 32 + a_koff);
                asm volatile("ldmatrix.sync.aligned.m8n8.x4.shared.b16 {%0,%1,%2,%3}, [%4];"
                             : "=r"(af[mt][0]), "=r"(af[mt][1]), "=r"(af[mt][2]), "=r"(af[mt][3])
                             : "r"(addr));
            }
#pragma unroll
            for (int nt = 0; nt < 4; ++nt) {
                uint32_t addr = bS + (uint32_t)((wn + nt * 8 + b_roff) * ROWB + kk * 32 + b_koff);
                asm volatile("ldmatrix.sync.aligned.m8n8.x2.shared.b16 {%0,%1}, [%2];"
                             : "=r"(bf[nt][0]), "=r"(bf[nt][1])
                             : "r"(addr));
            }
#pragma unroll
            for (int mt = 0; mt < 4; ++mt)
#pragma unroll
                for (int nt = 0; nt < 4; ++nt) {
                    asm volatile(
                        "mma.sync.aligned.m16n8k16.row.col.f32.bf16.bf16.f32 "
                        "{%0,%1,%2,%3},{%4,%5,%6,%7},{%8,%9},{%0,%1,%2,%3};"
                        : "+f"(acc[mt][nt][0]), "+f"(acc[mt][nt][1]),
                          "+f"(acc[mt][nt][2]), "+f"(acc[mt][nt][3])
                        : "r"(af[mt][0]), "r"(af[mt][1]), "r"(af[mt][2]), "r"(af[mt][3]),
                          "r"(bf[nt][0]), "r"(bf[nt][1]));
                }
        }
    }

    // ---- flag near-zero logits (warp-aggregated single atomic) ----
    {
        unsigned lf[LF_CAP];
        unsigned lc = 0;
#pragma unroll
        for (int mt = 0; mt < 4; ++mt)
#pragma unroll
            for (int nt = 0; nt < 4; ++nt)
#pragma unroll
                for (int q = 0; q < 4; ++q) {
                    if (fabsf(acc[mt][nt][q]) < TAU) {
                        int m = bm + wm + mt * 16 + ((q & 2) * 4) + (lane >> 2);
                        int n = bn + wn + nt * 8 + (lane & 3) * 2 + (q & 1);
                        unsigned enc = ((unsigned)m << 10) | (unsigned)n;
                        if (lc < LF_CAP) lf[lc] = enc;
                        else {   // ultra-rare overflow: direct (still correct)
                            unsigned idx = atomicAdd(&g_nflags, 1u);
                            if (idx < FLAG_CAP) g_flags[idx] = enc;
                        }
                        lc++;
                    }
                }
        unsigned cnt = (lc > LF_CAP) ? LF_CAP : lc;
        // warp inclusive scan of cnt
        unsigned off = cnt;
#pragma unroll
        for (int d = 1; d < 32; d <<= 1) {
            unsigned n = __shfl_up_sync(0xffffffffu, off, d);
            if (lane >= d) off += n;
        }
        unsigned wtot = __shfl_sync(0xffffffffu, off, 31);
        unsigned base = 0;
        if (wtot) {
            if (lane == 31) base = atomicAdd(&g_nflags, wtot);
            base = __shfl_sync(0xffffffffu, base, 31);
            unsigned my = base + off - cnt;
            for (unsigned j = 0; j < cnt; ++j)
                if (my + j < FLAG_CAP) g_flags[my + j] = lf[j];
        }
    }

    // ---- sign pack: n-tile (8 cols) == one code byte ----
    __syncthreads();
    unsigned char* spack = (unsigned char*)smem;
    const int bytecol = (wn >> 3);
#pragma unroll
    for (int mt = 0; mt < 4; ++mt) {
#pragma unroll
        for (int nt = 0; nt < 4; ++nt) {
            unsigned v0 = ((acc[mt][nt][0] > 0.0f) ? 1u : 0u) | ((acc[mt][nt][1] > 0.0f) ? 2u : 0u);
            unsigned v1 = ((acc[mt][nt][2] > 0.0f) ? 1u : 0u) | ((acc[mt][nt][3] > 0.0f) ? 2u : 0u);
            v0 <<= 2 * (lane & 3);
            v1 <<= 2 * (lane & 3);
            v0 |= __shfl_xor_sync(0xffffffffu, v0, 1);
            v0 |= __shfl_xor_sync(0xffffffffu, v0, 2);
            v1 |= __shfl_xor_sync(0xffffffffu, v1, 1);
            v1 |= __shfl_xor_sync(0xffffffffu, v1, 2);
            if ((lane & 3) == 0) {
                int r = lane >> 2;
                int row0 = wm + mt * 16 + r;
                spack[row0 * 16 + bytecol + nt]       = (unsigned char)v0;
                spack[(row0 + 8) * 16 + bytecol + nt] = (unsigned char)v1;
            }
        }
    }
    __syncthreads();

    if (tid < BM) {
        int mg = bm + tid;
        int b  = mg >> 10;
        int t  = mg & 1023;
        int sc = bn >> 8;
        int r0 = (bn & 255) >> 3;
        uint4 val = *(uint4*)(spack + tid * 16);
        *(uint4*)(g_codes + ((size_t)((b * S_ + sc) * T_ + t) * R_) + r0) = val;
    }
}

// ---------------- kernel 3: fp32 fixup of flagged logits ----------------
__global__ __launch_bounds__(256)
void fixup_kernel(const float* __restrict__ hidden, const float* __restrict__ qw)
{
    unsigned count = g_nflags;
    if (count > FLAG_CAP) count = FLAG_CAP;
    unsigned i = blockIdx.x * blockDim.x + threadIdx.x;
    const unsigned stride = gridDim.x * blockDim.x;
    for (; i < count; i += stride) {
        unsigned e = g_flags[i];
        int m = (int)(e >> 10);
        int n = (int)(e & 1023);
        const float4* pa = (const float4*)(hidden + (size_t)m * GK);
        const float4* pw = (const float4*)(qw + (size_t)n * GK);
        float d = 0.0f;
#pragma unroll 8
        for (int k = 0; k < GK / 4; ++k) {
            float4 a = __ldg(pa + k);
            float4 wv = __ldg(pw + k);
            d = fmaf(a.x, wv.x, d);
            d = fmaf(a.y, wv.y, d);
            d = fmaf(a.z, wv.z, d);
            d = fmaf(a.w, wv.w, d);
        }
        int b  = m >> 10;
        int t  = m & 1023;
        int s  = n >> 8;
        int r  = (n & 255) >> 3;
        int bit = n & 7;
        unsigned byte_off = (unsigned)(((b * S_ + s) * T_ + t) * R_ + r);
        unsigned* wp = (unsigned*)g_codes + (byte_off >> 2);
        unsigned shift = (byte_off & 3u) * 8u + (unsigned)bit;
        if (d > 0.0f) atomicOr(wp, 1u << shift);
        else          atomicAnd(wp, ~(1u << shift));
    }
}

// ---------------- kernel 4: gather (ILP 4, straight-line, no local arrays) ----------------
#define NUNITS (B_ * S_ * V_ * R_ * 2)      // 523776
#define GSTRIDE 131072                       // 512 blocks * 256 threads
__global__ __launch_bounds__(256)
void gather_kernel(const float* __restrict__ flat, float* __restrict__ out)
{
    const int tid0 = blockIdx.x * blockDim.x + threadIdx.x;

    const float4* s0; const float4* s1; const float4* s2; const float4* s3;
    float4 *d0, *d1, *d2, *d3;
    bool p3;

    {
        int idx = tid0;                       // always < NUNITS
        int half = idx & 1;  int row = idx >> 1;
        int r = row & 31;    int q = row >> 5;
        int v = q % V_;      int bs = q / V_;
        unsigned addr = (unsigned)g_codes[(size_t)(bs * T_ + v) * R_ + r]
                      | ((unsigned)g_codes[(size_t)(bs * T_ + v) * R_ + r + R_] << 8);
        unsigned gidx = (unsigned)(bs & 3) * SUB_STRIDE + (unsigned)r * ROUTE_VOCAB + addr;
        s0 = (const float4*)(flat + (size_t)gidx * M_) + half;
        d0 = (float4*)(out + (size_t)row * M_) + half;
    }
    {
        int idx = tid0 + GSTRIDE;
        int half = idx & 1;  int row = idx >> 1;
        int r = row & 31;    int q = row >> 5;
        int v = q % V_;      int bs = q / V_;
        unsigned addr = (unsigned)g_codes[(size_t)(bs * T_ + v) * R_ + r]
                      | ((unsigned)g_codes[(size_t)(bs * T_ + v) * R_ + r + R_] << 8);
        unsigned gidx = (unsigned)(bs & 3) * SUB_STRIDE + (unsigned)r * ROUTE_VOCAB + addr;
        s1 = (const float4*)(flat + (size_t)gidx * M_) + half;
        d1 = (float4*)(out + (size_t)row * M_) + half;
    }
    {
        int idx = tid0 + 2 * GSTRIDE;
        int half = idx & 1;  int row = idx >> 1;
        int r = row & 31;    int q = row >> 5;
        int v = q % V_;      int bs = q / V_;
        unsigned addr = (unsigned)g_codes[(size_t)(bs * T_ + v) * R_ + r]
                      | ((unsigned)g_codes[(size_t)(bs * T_ + v) * R_ + r + R_] << 8);
        unsigned gidx = (unsigned)(bs & 3) * SUB_STRIDE + (unsigned)r * ROUTE_VOCAB + addr;
        s2 = (const float4*)(flat + (size_t)gidx * M_) + half;
        d2 = (float4*)(out + (size_t)row * M_) + half;
    }
    {
        int idx = tid0 + 3 * GSTRIDE;
        p3 = idx < NUNITS;
        int cidx = p3 ? idx : 0;
        int half = cidx & 1;  int row = cidx >> 1;
        int r = row & 31;     int q = row >> 5;
        int v = q % V_;       int bs = q / V_;
        unsigned addr = (unsigned)g_codes[(size_t)(bs * T_ + v) * R_ + r]
                      | ((unsigned)g_codes[(size_t)(bs * T_ + v) * R_ + r + R_] << 8);
        unsigned gidx = (unsigned)(bs & 3) * SUB_STRIDE + (unsigned)r * ROUTE_VOCAB + addr;
        s3 = (const float4*)(flat + (size_t)gidx * M_) + half;
        d3 = (float4*)(out + (size_t)row * M_) + half;
    }

    float4 v0 = __ldg(s0);
    float4 v1 = __ldg(s1);
    float4 v2 = __ldg(s2);
    float4 v3 = p3 ? __ldg(s3) : make_float4(0.f, 0.f, 0.f, 0.f);

    *d0 = v0;
    *d1 = v1;
    *d2 = v2;
    if (p3) *d3 = v3;
}

// ---------------- launch ----------------
extern "C" void kernel_launch(void* const* d_in, const int* in_sizes, int n_in,
                              void* d_out, int out_size)
{
    (void)in_sizes; (void)n_in; (void)out_size;
    const float* hidden = (const float*)d_in[0];
    const float* qw     = (const float*)d_in[1];
    const float* fw     = (const float*)d_in[2];
    float* out          = (float*)d_out;

    cudaFuncSetAttribute(gemm_mma_kernel, cudaFuncAttributeMaxDynamicSharedMemorySize, SMEM_SZ);

    split_kernel<<<384, 256>>>(hidden, qw);

    dim3 grid(GN / BN, GM / BM);   // (8, 16)
    gemm_mma_kernel<<<grid, 256, SMEM_SZ>>>();

    fixup_kernel<<<256, 256>>>(hidden, qw);

    gather_kernel<<<512, 256>>>(fw, out);
}

// round 8
// speedup vs baseline: 1.1675x; 1.0165x over previous
#include <cuda_runtime.h>
#include <cuda_bf16.h>
#include <cstdint>

// ---------------- problem constants ----------------
#define B_ 2
#define T_ 1024
#define S_ 4
#define R_ 32
#define V_ 1023
#define M_ 8
#define ROUTE_VOCAB 65536
#define SUB_STRIDE  (R_ * ROUTE_VOCAB)

#define GM 2048
#define GN 1024
#define GK 256

// ---------------- mma.sync GEMM tiling ----------------
#define BM 128
#define BN 128
#define BK 32
#define NK (GK / BK)               // 8 chunk iterations
#define STAGES 4
#define ROWB 80                    // smem bytes/row: 64B data + 16B pad (conflict-free)
#define STAGE_A (BM * ROWB)
#define STAGE_B (BN * ROWB)
#define STAGE_SZ (STAGE_A + STAGE_B)
#define SMEM_SZ (STAGES * STAGE_SZ)   // 81920

#define TAU 0.005f
#define FCAP 1024                  // per-CTA flag list capacity (mean ~205)

// epilogue smem layout (reuses stage memory)
#define SP_BYTES 2048              // spack: 128 rows x 16 bytes
#define CNT_OFF  2048
#define LIST_OFF 2064

// ---------------- device scratch ----------------
__device__ __nv_bfloat16 gA[GM * GK];          // bf16 round of hidden
__device__ __nv_bfloat16 gW[GN * GK];          // bf16 round of q_weight
__device__ __align__(16) unsigned char g_codes[B_ * S_ * T_ * R_];

__device__ __forceinline__ uint32_t smem_u32(const void* p) {
    uint32_t a;
    asm("{ .reg .u64 t; cvta.to.shared.u64 t, %1; cvt.u32.u64 %0, t; }" : "=r"(a) : "l"(p));
    return a;
}

// ---------------- kernel 1: fp32 -> bf16 round ----------------
__global__ __launch_bounds__(256) void split_kernel(const float* __restrict__ A,
                                                    const float* __restrict__ W)
{
    const int NA4 = GM * GK / 4;   // 131072
    const int NW4 = GN * GK / 4;   // 65536
    int base = (blockIdx.x * blockDim.x + threadIdx.x) * 2;
#pragma unroll
    for (int u = 0; u < 2; ++u) {
        int i = base + u;
        const float* src; __nv_bfloat16* dst; int b4;
        if (i < NA4)            { src = A; dst = gA; b4 = i; }
        else if (i < NA4 + NW4) { src = W; dst = gW; b4 = i - NA4; }
        else continue;
        float4 v = ((const float4*)src)[b4];
        unsigned short l0 = __bfloat16_as_ushort(__float2bfloat16_rn(v.x));
        unsigned short l1 = __bfloat16_as_ushort(__float2bfloat16_rn(v.y));
        unsigned short l2 = __bfloat16_as_ushort(__float2bfloat16_rn(v.z));
        unsigned short l3 = __bfloat16_as_ushort(__float2bfloat16_rn(v.w));
        uint2 u2;
        u2.x = (uint32_t)l0 | ((uint32_t)l1 << 16);
        u2.y = (uint32_t)l2 | ((uint32_t)l3 << 16);
        ((uint2*)dst)[b4] = u2;
    }
}

// ---------------- kernel 2: mma GEMM + in-CTA fp32 fixup + sign pack ----------------
__device__ __forceinline__ void load_stage(uint32_t sbase, int c, int bm, int bn, int tid)
{
    int k0 = c * BK;
    const __nv_bfloat16* bA = gA + (size_t)bm * GK + k0;
    const __nv_bfloat16* bW = gW + (size_t)bn * GK + k0;
    uint32_t stg = sbase + (uint32_t)(c % STAGES) * STAGE_SZ;
#pragma unroll
    for (int j = 0; j < 2; ++j) {
        int id  = tid + j * 256;
        int row = id >> 2;
        int c4  = id & 3;
        uint32_t da = stg + (uint32_t)(row * ROWB + c4 * 16);
        asm volatile("cp.async.cg.shared.global [%0], [%1], 16;"
                     :: "r"(da), "l"(bA + (size_t)row * GK + c4 * 8));
        uint32_t db = stg + STAGE_A + (uint32_t)(row * ROWB + c4 * 16);
        asm volatile("cp.async.cg.shared.global [%0], [%1], 16;"
                     :: "r"(db), "l"(bW + (size_t)row * GK + c4 * 8));
    }
    asm volatile("cp.async.commit_group;" ::: "memory");
}

__device__ __forceinline__ float dot_fp32(const float* __restrict__ hidden,
                                          const float* __restrict__ qw,
                                          int m, int n)
{
    const float4* pa = (const float4*)(hidden + (size_t)m * GK);
    const float4* pw = (const float4*)(qw + (size_t)n * GK);
    float d = 0.0f;
#pragma unroll 8
    for (int k = 0; k < GK / 4; ++k) {
        float4 a = __ldg(pa + k);
        float4 wv = __ldg(pw + k);
        d = fmaf(a.x, wv.x, d);
        d = fmaf(a.y, wv.y, d);
        d = fmaf(a.z, wv.z, d);
        d = fmaf(a.w, wv.w, d);
    }
    return d;
}

__global__ __launch_bounds__(256, 1)
void gemm_mma_kernel(const float* __restrict__ hidden, const float* __restrict__ qw)
{
    extern __shared__ __align__(16) char smem[];
    const uint32_t sbase = smem_u32(smem);
    const int tid  = threadIdx.x;
    const int w    = tid >> 5;
    const int lane = tid & 31;
    const int bm = blockIdx.y * BM, bn = blockIdx.x * BN;
    const int wm = (w & 1) * 64;
    const int wn = (w >> 1) * 32;

    const int lrow = lane & 7;
    const int lmat = lane >> 3;
    const int a_roff = (lmat & 1) * 8 + lrow;
    const int a_koff = (lmat >> 1) * 16;
    const int l16  = lane & 15;
    const int b_roff = l16 & 7;
    const int b_koff = (l16 >> 3) * 16;

    float acc[4][4][4];
#pragma unroll
    for (int i = 0; i < 4; i++)
#pragma unroll
        for (int j = 0; j < 4; j++)
#pragma unroll
            for (int q = 0; q < 4; q++) acc[i][j][q] = 0.0f;

    load_stage(sbase, 0, bm, bn, tid);
    load_stage(sbase, 1, bm, bn, tid);
    load_stage(sbase, 2, bm, bn, tid);

    for (int c = 0; c < NK; ++c) {
        asm volatile("cp.async.wait_group 2;" ::: "memory");
        __syncthreads();
        if (c + 3 < NK) load_stage(sbase, c + 3, bm, bn, tid);

        uint32_t aS = sbase + (uint32_t)(c % STAGES) * STAGE_SZ;
        uint32_t bS = aS + STAGE_A;

#pragma unroll
        for (int kk = 0; kk < 2; ++kk) {
            uint32_t af[4][4];
            uint32_t bf[4][2];
#pragma unroll
            for (int mt = 0; mt < 4; ++mt) {
                uint32_t addr = aS + (uint32_t)((wm + mt * 16 + a_roff) * ROWB + kk * 32 + a_koff);
                asm volatile("ldmatrix.sync.aligned.m8n8.x4.shared.b16 {%0,%1,%2,%3}, [%4];"
                             : "=r"(af[mt][0]), "=r"(af[mt][1]), "=r"(af[mt][2]), "=r"(af[mt][3])
                             : "r"(addr));
            }
#pragma unroll
            for (int nt = 0; nt < 4; ++nt) {
                uint32_t addr = bS + (uint32_t)((wn + nt * 8 + b_roff) * ROWB + kk * 32 + b_koff);
                asm volatile("ldmatrix.sync.aligned.m8n8.x2.shared.b16 {%0,%1}, [%2];"
                             : "=r"(bf[nt][0]), "=r"(bf[nt][1])
                             : "r"(addr));
            }
#pragma unroll
            for (int mt = 0; mt < 4; ++mt)
#pragma unroll
                for (int nt = 0; nt < 4; ++nt) {
                    asm volatile(
                        "mma.sync.aligned.m16n8k16.row.col.f32.bf16.bf16.f32 "
                        "{%0,%1,%2,%3},{%4,%5,%6,%7},{%8,%9},{%0,%1,%2,%3};"
                        : "+f"(acc[mt][nt][0]), "+f"(acc[mt][nt][1]),
                          "+f"(acc[mt][nt][2]), "+f"(acc[mt][nt][3])
                        : "r"(af[mt][0]), "r"(af[mt][1]), "r"(af[mt][2]), "r"(af[mt][3]),
                          "r"(bf[nt][0]), "r"(bf[nt][1]));
                }
        }
    }

    // ---- epilogue: flag -> pack -> cooperative fp32 fixup -> store ----
    unsigned char* spack = (unsigned char*)smem;
    unsigned* scnt = (unsigned*)(smem + CNT_OFF);
    unsigned* slist = (unsigned*)(smem + LIST_OFF);

    if (tid == 0) *scnt = 0;
    __syncthreads();   // compute done (stages dead), counter ready

    // flag near-zero logits into CTA-local smem list
#pragma unroll
    for (int mt = 0; mt < 4; ++mt)
#pragma unroll
        for (int nt = 0; nt < 4; ++nt)
#pragma unroll
            for (int q = 0; q < 4; ++q) {
                if (fabsf(acc[mt][nt][q]) < TAU) {
                    int ml = wm + mt * 16 + ((q & 2) * 4) + (lane >> 2);
                    int nl = wn + nt * 8 + (lane & 3) * 2 + (q & 1);
                    unsigned idx = atomicAdd(scnt, 1u);
                    if (idx < FCAP) slist[idx] = ((unsigned)ml << 7) | (unsigned)nl;
                    else  // essentially-never overflow: exact inline recompute
                        acc[mt][nt][q] = dot_fp32(hidden, qw, bm + ml, bn + nl);
                }
            }

    // sign pack: n-tile (8 cols) == one code byte
    const int bytecol = (wn >> 3);
#pragma unroll
    for (int mt = 0; mt < 4; ++mt) {
#pragma unroll
        for (int nt = 0; nt < 4; ++nt) {
            unsigned v0 = ((acc[mt][nt][0] > 0.0f) ? 1u : 0u) | ((acc[mt][nt][1] > 0.0f) ? 2u : 0u);
            unsigned v1 = ((acc[mt][nt][2] > 0.0f) ? 1u : 0u) | ((acc[mt][nt][3] > 0.0f) ? 2u : 0u);
            v0 <<= 2 * (lane & 3);
            v1 <<= 2 * (lane & 3);
            v0 |= __shfl_xor_sync(0xffffffffu, v0, 1);
            v0 |= __shfl_xor_sync(0xffffffffu, v0, 2);
            v1 |= __shfl_xor_sync(0xffffffffu, v1, 1);
            v1 |= __shfl_xor_sync(0xffffffffu, v1, 2);
            if ((lane & 3) == 0) {
                int r = lane >> 2;
                int row0 = wm + mt * 16 + r;
                spack[row0 * 16 + bytecol + nt]       = (unsigned char)v0;
                spack[(row0 + 8) * 16 + bytecol + nt] = (unsigned char)v1;
            }
        }
    }
    __syncthreads();   // pack + flag list complete

    // cooperative exact fixup: ~205 flags / 256 threads
    {
        unsigned cnt = *scnt;
        if (cnt > FCAP) cnt = FCAP;
        for (unsigned f = tid; f < cnt; f += 256) {
            unsigned e = slist[f];
            int ml = (int)(e >> 7);
            int nl = (int)(e & 127);
            float d = dot_fp32(hidden, qw, bm + ml, bn + nl);
            unsigned bytePos = (unsigned)(ml * 16 + (nl >> 3));
            unsigned wIdx = bytePos >> 2;
            unsigned sh = (bytePos & 3u) * 8u + (unsigned)(nl & 7);
            unsigned* sp32 = (unsigned*)spack;
            if (d > 0.0f) atomicOr(&sp32[wIdx], 1u << sh);
            else          atomicAnd(&sp32[wIdx], ~(1u << sh));
        }
    }
    __syncthreads();   // fixes visible

    if (tid < BM) {
        int mg = bm + tid;
        int b  = mg >> 10;
        int t  = mg & 1023;
        int sc = bn >> 8;
        int r0 = (bn & 255) >> 3;
        uint4 val = *(uint4*)(spack + tid * 16);
        *(uint4*)(g_codes + ((size_t)((b * S_ + sc) * T_ + t) * R_) + r0) = val;
    }
}

// ---------------- kernel 3: gather (ILP 4, straight-line) ----------------
#define NUNITS (B_ * S_ * V_ * R_ * 2)      // 523776
#define GSTRIDE 131072                       // 512 blocks * 256 threads
__global__ __launch_bounds__(256)
void gather_kernel(const float* __restrict__ flat, float* __restrict__ out)
{
    const int tid0 = blockIdx.x * blockDim.x + threadIdx.x;

    const float4* s0; const float4* s1; const float4* s2; const float4* s3;
    float4 *d0, *d1, *d2, *d3;
    bool p3;

    {
        int idx = tid0;
        int half = idx & 1;  int row = idx >> 1;
        int r = row & 31;    int q = row >> 5;
        int v = q % V_;      int bs = q / V_;
        unsigned addr = (unsigned)g_codes[(size_t)(bs * T_ + v) * R_ + r]
                      | ((unsigned)g_codes[(size_t)(bs * T_ + v) * R_ + r + R_] << 8);
        unsigned gidx = (unsigned)(bs & 3) * SUB_STRIDE + (unsigned)r * ROUTE_VOCAB + addr;
        s0 = (const float4*)(flat + (size_t)gidx * M_) + half;
        d0 = (float4*)(out + (size_t)row * M_) + half;
    }
    {
        int idx = tid0 + GSTRIDE;
        int half = idx & 1;  int row = idx >> 1;
        int r = row & 31;    int q = row >> 5;
        int v = q % V_;      int bs = q / V_;
        unsigned addr = (unsigned)g_codes[(size_t)(bs * T_ + v) * R_ + r]
                      | ((unsigned)g_codes[(size_t)(bs * T_ + v) * R_ + r + R_] << 8);
        unsigned gidx = (unsigned)(bs & 3) * SUB_STRIDE + (unsigned)r * ROUTE_VOCAB + addr;
        s1 = (const float4*)(flat + (size_t)gidx * M_) + half;
        d1 = (float4*)(out + (size_t)row * M_) + half;
    }
    {
        int idx = tid0 + 2 * GSTRIDE;
        int half = idx & 1;  int row = idx >> 1;
        int r = row & 31;    int q = row >> 5;
        int v = q % V_;      int bs = q / V_;
        unsigned addr = (unsigned)g_codes[(size_t)(bs * T_ + v) * R_ + r]
                      | ((unsigned)g_codes[(size_t)(bs * T_ + v) * R_ + r + R_] << 8);
        unsigned gidx = (unsigned)(bs & 3) * SUB_STRIDE + (unsigned)r * ROUTE_VOCAB + addr;
        s2 = (const float4*)(flat + (size_t)gidx * M_) + half;
        d2 = (float4*)(out + (size_t)row * M_) + half;
    }
    {
        int idx = tid0 + 3 * GSTRIDE;
        p3 = idx < NUNITS;
        int cidx = p3 ? idx : 0;
        int half = cidx & 1;  int row = cidx >> 1;
        int r = row & 31;     int q = row >> 5;
        int v = q % V_;       int bs = q / V_;
        unsigned addr = (unsigned)g_codes[(size_t)(bs * T_ + v) * R_ + r]
                      | ((unsigned)g_codes[(size_t)(bs * T_ + v) * R_ + r + R_] << 8);
        unsigned gidx = (unsigned)(bs & 3) * SUB_STRIDE + (unsigned)r * ROUTE_VOCAB + addr;
        s3 = (const float4*)(flat + (size_t)gidx * M_) + half;
        d3 = (float4*)(out + (size_t)row * M_) + half;
    }

    float4 v0 = __ldg(s0);
    float4 v1 = __ldg(s1);
    float4 v2 = __ldg(s2);
    float4 v3 = p3 ? __ldg(s3) : make_float4(0.f, 0.f, 0.f, 0.f);

    *d0 = v0;
    *d1 = v1;
    *d2 = v2;
    if (p3) *d3 = v3;
}

// ---------------- launch ----------------
extern "C" void kernel_launch(void* const* d_in, const int* in_sizes, int n_in,
                              void* d_out, int out_size)
{
    (void)in_sizes; (void)n_in; (void)out_size;
    const float* hidden = (const float*)d_in[0];
    const float* qw     = (const float*)d_in[1];
    const float* fw     = (const float*)d_in[2];
    float* out          = (float*)d_out;

    cudaFuncSetAttribute(gemm_mma_kernel, cudaFuncAttributeMaxDynamicSharedMemorySize, SMEM_SZ);

    split_kernel<<<384, 256>>>(hidden, qw);

    dim3 grid(GN / BN, GM / BM);   // (8, 16)
    gemm_mma_kernel<<<grid, 256, SMEM_SZ>>>(hidden, qw);

    gather_kernel<<<512, 256>>>(fw, out);
}